// round 14
// baseline (speedup 1.0000x reference)
#include <cuda_runtime.h>
#include <cstdint>
#include <cstddef>

// Problem constants
#define EN    1000000
#define NN    100000
#define EORI  200000
#define DD    128
#define RR    32
#define HH    128
#define NRELC 200
#define L2E   1.4426950408889634f

#define TILE_E 64
#define NT64  15625         // EN / 64 exactly
#define GRID1 296           // 2 CTAs per SM

#define AS_STRIDE 132       // floats; conflict-free A-fragment LDS
#define BS_STRIDE 132       // floats; [n][perm(k)] rows (bank-verified)

// smem offsets (uint32 units), per CTA
#define BS_OFF   0
#define AS_OFF   (128 * BS_STRIDE)                    // 16896
#define STAT_OFF (AS_OFF + TILE_E * AS_STRIDE)        // 25344
#define STG_OFF  (STAT_OFF + 256)                     // 25600
#define SMEM_U32 (STG_OFF + 8 * 320)                  // 28160 -> 112640 B

// ---------------- scratch globals ----------------
__device__ float g_h[(size_t)EN * HH];   // 512 MB pre-BN activations
__device__ float g_w[EN];                // exp(w) per edge
__device__ float g_sum[HH];
__device__ float g_sumsq[HH];
__device__ float g_nsum[NN];             // per-node softmax denominator
__device__ unsigned char g_flag[EN];     // is-original-edge flag
__device__ float g_prec[NRELC * HH];

// ---------------- helpers ----------------
__device__ __forceinline__ uint32_t tf32u(float x) {
    uint32_t o; asm("cvt.rna.tf32.f32 %0, %1;" : "=r"(o) : "f"(x)); return o;
}
__device__ __forceinline__ void mma_tf32(float c[4], const uint32_t a[4],
                                         const uint32_t b[2]) {
    asm volatile(
        "mma.sync.aligned.m16n8k8.row.col.f32.tf32.tf32.f32 "
        "{%0,%1,%2,%3}, {%4,%5,%6,%7}, {%8,%9}, {%0,%1,%2,%3};"
        : "+f"(c[0]), "+f"(c[1]), "+f"(c[2]), "+f"(c[3])
        : "r"(a[0]), "r"(a[1]), "r"(a[2]), "r"(a[3]), "r"(b[0]), "r"(b[1]));
}
// pack k and k+4 adjacent: one LDS.64 per B fragment
__device__ __forceinline__ int permk(int k) {
    return (k & ~7) | ((k & 3) << 1) | ((k >> 2) & 1);
}

// ---------------- setup kernels ----------------
__global__ void k_setup(const float* __restrict__ rel,
                        const float* __restrict__ W0,
                        const float* __restrict__ b0) {
    int i = blockIdx.x * blockDim.x + threadIdx.x;
    if (i < HH) { g_sum[i] = 0.f; g_sumsq[i] = 0.f; }
    if (i < NN) g_nsum[i] = 0.f;
    if (i < EN) g_flag[i] = 0;
    if (i < NRELC * HH) {
        int r = i / HH, c = i % HH;
        float s = b0[c];
#pragma unroll
        for (int k = 0; k < RR; k++)
            s = fmaf(rel[r * RR + k], W0[(DD + k) * HH + c], s);
        g_prec[i] = s;
    }
}
__global__ void k_flag(const int* __restrict__ ori) {
    int i = blockIdx.x * blockDim.x + threadIdx.x;
    if (i < EORI) g_flag[ori[i]] = 1;
}

// ---------------- pass1 ------------------------------------------------------
// 296 CTAs x 256 threads, 2 CTAs/SM. Tile = 64 edges x 128 ch, K = 128.
// Warp grid 2(m) x 4(n); warp tile 32x32 via m16n8k8 tf32. Single As buffer;
// independent CTAs drift in phase, so one CTA's gather stall hides under the
// other CTA's MMA on the same SMSPs. EN % 64 == 0: no bounds checks.

__device__ __forceinline__ void produce64(uint32_t* __restrict__ As,
                                          const float* __restrict__ nf,
                                          const int* __restrict__ rowv,
                                          const int* __restrict__ colv,
                                          int tile, int wid, int lane) {
    const int e0 = tile * TILE_E + wid * 8;
    int idx = 0;
    if (lane < 16) {
        int q = e0 + (lane & 7);
        idx = (lane < 8) ? rowv[q] : colv[q];
    }
#pragma unroll 2
    for (int i = 0; i < 8; i++) {
        const int rn = __shfl_sync(0xffffffffu, idx, i);
        const int cn = __shfl_sync(0xffffffffu, idx, i + 8);
        float4 a = *(const float4*)(nf + (size_t)rn * DD + lane * 4);
        float4 b = *(const float4*)(nf + (size_t)cn * DD + lane * 4);
        uint4 s;
        s.x = tf32u(exp2f(-L2E * fabsf(a.x - b.x)));
        s.y = tf32u(exp2f(-L2E * fabsf(a.y - b.y)));
        s.z = tf32u(exp2f(-L2E * fabsf(a.z - b.z)));
        s.w = tf32u(exp2f(-L2E * fabsf(a.w - b.w)));
        *(uint4*)(As + (wid * 8 + i) * AS_STRIDE + lane * 4) = s;
    }
}

__global__ __launch_bounds__(256, 2) void k_pass1(
    const float* __restrict__ nf,
    const float* __restrict__ W0,
    const int* __restrict__ rowv,
    const int* __restrict__ colv,
    const int* __restrict__ etype) {
    extern __shared__ uint32_t sm[];
    uint32_t* Bs = sm + BS_OFF;              // [128 n][BS_STRIDE perm-k]
    uint32_t* As = sm + AS_OFF;              // [64 m][AS_STRIDE k]
    float* ssum = (float*)(sm + STAT_OFF);
    float* ssq  = ssum + 128;

    const int tid = threadIdx.x;
    const int wid = tid >> 5, lane = tid & 31;
    const int gid = lane >> 2, tg = lane & 3;
    const int wm = wid >> 2, wn = wid & 3;   // 2 x 4 warp grid
    const int m0 = wm * 32, n0 = wn * 32;
    float2* stg = (float2*)(sm + STG_OFF) + wid * 160;  // 8 rows x 20 float2

    // B = W0[:128,:] tf32 bits, [n][perm(k)]
    for (int i = tid; i < 128 * 128; i += 256) {
        int k = i >> 7, n = i & 127;
        Bs[n * BS_STRIDE + permk(k)] = tf32u(W0[i]);
    }
    if (tid < HH) { ssum[tid] = 0.f; ssq[tid] = 0.f; }
    __syncthreads();

    // per-thread BN accumulators; col(nt,h) = n0 + nt*8 + tg*2 + h
    float ps[8], pq[8];
#pragma unroll
    for (int i = 0; i < 8; i++) { ps[i] = 0.f; pq[i] = 0.f; }

    for (int tile = blockIdx.x; tile < NT64; tile += GRID1) {
        // ---- produce sim tile (64 edges) into As ----
        produce64(As, nf, rowv, colv, tile, wid, lane);
        __syncthreads();

        // prefetch etype for this warp's 4 epilogue chunks (hides under MMA)
        int et4[4];
#pragma unroll
        for (int q = 0; q < 4; q++) {
            const int row = m0 + (q >> 1) * 16 + (q & 1) * 8 + gid;
            et4[q] = etype[tile * TILE_E + row];
        }

        // ---- MMA: 2 m-tiles x 4 n-tiles x 16 k-tiles ----
        float acc[2][4][4];
#pragma unroll
        for (int mt = 0; mt < 2; mt++)
#pragma unroll
            for (int nt = 0; nt < 4; nt++)
#pragma unroll
                for (int r = 0; r < 4; r++) acc[mt][nt][r] = 0.f;

#pragma unroll
        for (int kt = 0; kt < 16; kt++) {
            const int k0 = kt * 8;
            uint32_t afr[2][4];
#pragma unroll
            for (int mt = 0; mt < 2; mt++) {
                const uint32_t* ab = As + (m0 + mt * 16 + gid) * AS_STRIDE + k0 + tg;
                afr[mt][0] = ab[0];
                afr[mt][1] = ab[8 * AS_STRIDE];
                afr[mt][2] = ab[4];
                afr[mt][3] = ab[8 * AS_STRIDE + 4];
            }
            uint32_t bfr[4][2];
#pragma unroll
            for (int nt = 0; nt < 4; nt++) {
                uint2 bb = *(const uint2*)(Bs + (n0 + nt * 8 + gid) * BS_STRIDE
                                           + k0 + tg * 2);
                bfr[nt][0] = bb.x;
                bfr[nt][1] = bb.y;
            }
#pragma unroll
            for (int mt = 0; mt < 2; mt++)
#pragma unroll
                for (int nt = 0; nt < 4; nt++)
                    mma_tf32(acc[mt][nt], afr[mt], bfr[nt]);
        }
        __syncthreads();   // As free for next produce (epilogue doesn't use As)

        // ---- epilogue: 4 chunks of 8 rows, staged, coalesced STG.128 ----
#pragma unroll
        for (int mt = 0; mt < 2; mt++) {
#pragma unroll
            for (int rr = 0; rr < 2; rr++) {
                const int rbase = tile * TILE_E + m0 + mt * 16 + rr * 8;
                const int et = et4[mt * 2 + rr];
                const float2* prow = (const float2*)(g_prec + et * HH);
#pragma unroll
                for (int nt = 0; nt < 4; nt++) {
                    const int c2g = (n0 + nt * 8 + tg * 2) >> 1;
                    float2 p = prow[c2g];
                    float v0 = acc[mt][nt][rr * 2 + 0] + p.x;
                    float v1 = acc[mt][nt][rr * 2 + 1] + p.y;
                    stg[gid * 20 + nt * 4 + tg] = make_float2(v0, v1);
                    ps[nt * 2 + 0] += v0; pq[nt * 2 + 0] = fmaf(v0, v0, pq[nt * 2 + 0]);
                    ps[nt * 2 + 1] += v1; pq[nt * 2 + 1] = fmaf(v1, v1, pq[nt * 2 + 1]);
                }
                __syncwarp();
#pragma unroll
                for (int s = 0; s < 2; s++) {
                    const int r = (lane >> 3) + s * 4;     // local row 0..7
                    const int c = lane & 7;                // float4 index
                    const int e = rbase + r;
                    float4 v = *(const float4*)((const float*)stg + r * 40 + c * 4);
                    __stcs((float4*)(g_h + (size_t)e * HH + n0 + c * 4), v);
                }
                __syncwarp();
            }
        }
    }

    // ---- final BN stat reduction: regs -> smem -> global ----
    __syncthreads();
#pragma unroll
    for (int nt = 0; nt < 4; nt++) {
#pragma unroll
        for (int h = 0; h < 2; h++) {
            const int col = n0 + nt * 8 + tg * 2 + h;
            atomicAdd(&ssum[col], ps[nt * 2 + h]);
            atomicAdd(&ssq[col], pq[nt * 2 + h]);
        }
    }
    __syncthreads();
    if (tid < HH) {
        atomicAdd(&g_sum[tid], ssum[tid]);
        atomicAdd(&g_sumsq[tid], ssq[tid]);
    }
}

// ---------------- pass3: BN params in-block, 8 edges/warp-iter ----------------
__global__ __launch_bounds__(256) void k_pass3(const int* __restrict__ colv,
                                               const float* __restrict__ W1,
                                               const float* __restrict__ b1,
                                               const float* __restrict__ gamma,
                                               const float* __restrict__ beta) {
    __shared__ float sgi[HH], ssh[HH];
    int tidb = threadIdx.x;
    if (tidb < HH) {
        float mu = g_sum[tidb] * (1.0f / EN);
        float var = g_sumsq[tidb] * (1.0f / EN) - mu * mu;
        float gi = gamma[tidb] * rsqrtf(var + 1e-5f);
        sgi[tidb] = gi;
        ssh[tidb] = beta[tidb] - mu * gi;
    }
    __syncthreads();

    const int lane = tidb & 31;
    const int warp = (blockIdx.x * blockDim.x + tidb) >> 5;
    const int nwarp = (gridDim.x * blockDim.x) >> 5;
    const float4 gi = *(const float4*)(sgi + lane * 4);
    const float4 sh = *(const float4*)(ssh + lane * 4);
    const float4 w1 = *(const float4*)(W1 + lane * 4);
    const float b1v = b1[0];

    for (int e = warp * 8; e < EN; e += nwarp * 8) {     // EN % 8 == 0
        float4 h[8];
#pragma unroll
        for (int j = 0; j < 8; j++)
            h[j] = __ldcs((const float4*)(g_h + (size_t)(e + j) * HH + lane * 4));
        int4 cn4a, cn4b;
        if (lane == 0) {
            cn4a = *(const int4*)(colv + e);
            cn4b = *(const int4*)(colv + e + 4);
        }

        float sdot[8];
#pragma unroll
        for (int j = 0; j < 8; j++) {
            float t, l, s;
            t = fmaf(h[j].x, gi.x, sh.x); l = fmaxf(t, 0.f) + 0.01f * fminf(t, 0.f); s = l * w1.x;
            t = fmaf(h[j].y, gi.y, sh.y); l = fmaxf(t, 0.f) + 0.01f * fminf(t, 0.f); s = fmaf(l, w1.y, s);
            t = fmaf(h[j].z, gi.z, sh.z); l = fmaxf(t, 0.f) + 0.01f * fminf(t, 0.f); s = fmaf(l, w1.z, s);
            t = fmaf(h[j].w, gi.w, sh.w); l = fmaxf(t, 0.f) + 0.01f * fminf(t, 0.f); s = fmaf(l, w1.w, s);
            sdot[j] = s;
        }
#pragma unroll
        for (int j = 0; j < 8; j++) {
            sdot[j] += __shfl_xor_sync(0xffffffffu, sdot[j], 16);
            sdot[j] += __shfl_xor_sync(0xffffffffu, sdot[j], 8);
            sdot[j] += __shfl_xor_sync(0xffffffffu, sdot[j], 4);
            sdot[j] += __shfl_xor_sync(0xffffffffu, sdot[j], 2);
            sdot[j] += __shfl_xor_sync(0xffffffffu, sdot[j], 1);
        }
        if (lane == 0) {
            float ev8[8];
            const int cns[8] = {cn4a.x, cn4a.y, cn4a.z, cn4a.w,
                                cn4b.x, cn4b.y, cn4b.z, cn4b.w};
#pragma unroll
            for (int j = 0; j < 8; j++) {
                float wv = sdot[j] + b1v;
                if (g_flag[e + j]) wv = 0.5f * wv + 0.5f;
                ev8[j] = exp2f(wv * L2E);
            }
            *(float4*)(g_w + e) = make_float4(ev8[0], ev8[1], ev8[2], ev8[3]);
            *(float4*)(g_w + e + 4) = make_float4(ev8[4], ev8[5], ev8[6], ev8[7]);
#pragma unroll
            for (int j = 0; j < 8; j++)
                atomicAdd(&g_nsum[cns[j]], ev8[j]);
        }
    }
}

// ---------------- pass5: vectorized x4 ----------------
__global__ void k_pass5(const int* __restrict__ colv, float* __restrict__ out) {
    int e = (blockIdx.x * blockDim.x + threadIdx.x) * 4;
    if (e >= EN) return;
    float4 w4 = *(const float4*)(g_w + e);
    int4 c4 = *(const int4*)(colv + e);
    float4 o;
    o.x = w4.x / g_nsum[c4.x];
    o.y = w4.y / g_nsum[c4.y];
    o.z = w4.z / g_nsum[c4.z];
    o.w = w4.w / g_nsum[c4.w];
    o.x = (o.x > 1e-4f) ? o.x : 0.f;
    o.y = (o.y > 1e-4f) ? o.y : 0.f;
    o.z = (o.z > 1e-4f) ? o.z : 0.f;
    o.w = (o.w > 1e-4f) ? o.w : 0.f;
    *(float4*)(out + e) = o;
}

// ---------------- launch ----------------
extern "C" void kernel_launch(void* const* d_in, const int* in_sizes, int n_in,
                              void* d_out, int out_size) {
    const float* n_feat  = (const float*)d_in[0];
    const float* rel_emb = (const float*)d_in[1];
    const float* W0      = (const float*)d_in[2];
    const float* b0      = (const float*)d_in[3];
    const float* gamma   = (const float*)d_in[4];
    const float* beta    = (const float*)d_in[5];
    const float* W1      = (const float*)d_in[6];
    const float* b1      = (const float*)d_in[7];
    const int*   rowv    = (const int*)d_in[8];
    const int*   colv    = (const int*)d_in[9];
    const int*   etype   = (const int*)d_in[10];
    const int*   ori     = (const int*)d_in[11];
    float* out = (float*)d_out;

    const int smem1 = SMEM_U32 * 4;   // 112,640 B per CTA
    static bool attr_done = false;
    if (!attr_done) {
        cudaFuncSetAttribute(k_pass1, cudaFuncAttributeMaxDynamicSharedMemorySize, smem1);
        attr_done = true;
    }

    k_setup<<<(EN + 255) / 256, 256>>>(rel_emb, W0, b0);
    k_flag<<<(EORI + 255) / 256, 256>>>(ori);
    k_pass1<<<GRID1, 256, smem1>>>(n_feat, W0, rowv, colv, etype);
    k_pass3<<<2048, 256>>>(colv, W1, b1, gamma, beta);
    k_pass5<<<(EN / 4 + 255) / 256, 256>>>(colv, out);
}

// round 16
// speedup vs baseline: 1.1630x; 1.1630x over previous
#include <cuda_runtime.h>
#include <cuda_fp16.h>
#include <cstdint>
#include <cstddef>

// Problem constants
#define EN    1000000
#define NN    100000
#define EORI  200000
#define DD    128
#define RR    32
#define HH    128
#define NRELC 200
#define L2E   1.4426950408889634f

#define NT    7813          // ceil(EN/128)
#define GRID1 148

#define AS_STRIDE 132       // floats; conflict-free A-fragment LDS
#define BS_STRIDE 136       // floats; [n][perm(k)] rows

// smem offsets (uint32 units)
#define BS_OFF   0
#define AS_OFF   (128 * BS_STRIDE)                    // 17408
#define ABUF_U32 (128 * AS_STRIDE)                    // 16896
#define STAT_OFF (AS_OFF + 2 * ABUF_U32)              // 51200
#define STG_OFF  (STAT_OFF + 256)                     // 51456
#define SMEM_U32 (STG_OFF + 16 * 160)                 // 54016 -> 216064 B

// ---------------- scratch globals ----------------
__device__ __half2 g_h2[(size_t)EN * 64];  // 256 MB pre-BN activations (fp16)
__device__ float g_w[EN];                  // exp(w) per edge
__device__ float g_sum[HH];
__device__ float g_sumsq[HH];
__device__ float g_nsum[NN];               // per-node softmax denominator
__device__ unsigned char g_flag[EN];       // is-original-edge flag
__device__ float g_prec[NRELC * HH];

// ---------------- helpers ----------------
__device__ __forceinline__ uint32_t tf32u(float x) {
    uint32_t o; asm("cvt.rna.tf32.f32 %0, %1;" : "=r"(o) : "f"(x)); return o;
}
__device__ __forceinline__ void mma_tf32(float c[4], const uint32_t a[4],
                                         const uint32_t b[2]) {
    asm volatile(
        "mma.sync.aligned.m16n8k8.row.col.f32.tf32.tf32.f32 "
        "{%0,%1,%2,%3}, {%4,%5,%6,%7}, {%8,%9}, {%0,%1,%2,%3};"
        : "+f"(c[0]), "+f"(c[1]), "+f"(c[2]), "+f"(c[3])
        : "r"(a[0]), "r"(a[1]), "r"(a[2]), "r"(a[3]), "r"(b[0]), "r"(b[1]));
}
// pack k and k+4 adjacent: one LDS.64 per B fragment
__device__ __forceinline__ int permk(int k) {
    return (k & ~7) | ((k & 3) << 1) | ((k >> 2) & 1);
}

// ---------------- setup kernels ----------------
__global__ void k_setup(const float* __restrict__ rel,
                        const float* __restrict__ W0,
                        const float* __restrict__ b0) {
    int i = blockIdx.x * blockDim.x + threadIdx.x;
    if (i < HH) { g_sum[i] = 0.f; g_sumsq[i] = 0.f; }
    if (i < NN) g_nsum[i] = 0.f;
    if (i < EN) g_flag[i] = 0;
    if (i < NRELC * HH) {
        int r = i / HH, c = i % HH;
        float s = b0[c];
#pragma unroll
        for (int k = 0; k < RR; k++)
            s = fmaf(rel[r * RR + k], W0[(DD + k) * HH + c], s);
        g_prec[i] = s;
    }
}
__global__ void k_flag(const int* __restrict__ ori) {
    int i = blockIdx.x * blockDim.x + threadIdx.x;
    if (i < EORI) g_flag[ori[i]] = 1;
}

// ---------------- pass1 ------------------------------------------------------
// Persistent 148 x 512 (16 warps). Tile = 128 edges x 128 ch, K = 128.
// Warp grid 4(m) x 4(n); warp tile 32x32 via m16n8k8 tf32.
// R13 (known-good) order: sync -> MMA(Ab) -> produce(t+GRID -> An) -> epilogue.
// g_h stored as fp16 (half2): halves the h-matrix DRAM traffic both ways.

__device__ __forceinline__ void produce128(uint32_t* __restrict__ As,
                                           const float* __restrict__ nf,
                                           const int* __restrict__ rowv,
                                           const int* __restrict__ colv,
                                           int tile, int wid, int lane) {
    const int e0 = tile * 128 + wid * 8;
    int idx = 0;
    {
        int q = e0 + (lane & 7);
        q = (q < EN) ? q : (EN - 1);
        if (lane < 16) idx = (lane < 8) ? rowv[q] : colv[q];
    }
#pragma unroll 2
    for (int i = 0; i < 8; i++) {
        const int rn = __shfl_sync(0xffffffffu, idx, i);
        const int cn = __shfl_sync(0xffffffffu, idx, i + 8);
        float4 a = *(const float4*)(nf + (size_t)rn * DD + lane * 4);
        float4 b = *(const float4*)(nf + (size_t)cn * DD + lane * 4);
        uint4 s;
        s.x = tf32u(exp2f(-L2E * fabsf(a.x - b.x)));
        s.y = tf32u(exp2f(-L2E * fabsf(a.y - b.y)));
        s.z = tf32u(exp2f(-L2E * fabsf(a.z - b.z)));
        s.w = tf32u(exp2f(-L2E * fabsf(a.w - b.w)));
        *(uint4*)(As + (wid * 8 + i) * AS_STRIDE + lane * 4) = s;
    }
}

__global__ __launch_bounds__(512, 1) void k_pass1(
    const float* __restrict__ nf,
    const float* __restrict__ W0,
    const int* __restrict__ rowv,
    const int* __restrict__ colv,
    const int* __restrict__ etype) {
    extern __shared__ uint32_t sm[];
    uint32_t* Bs = sm + BS_OFF;              // [128 n][BS_STRIDE perm-k]
    uint32_t* As0 = sm + AS_OFF;             // [128 m][AS_STRIDE k] x2
    uint32_t* As1 = As0 + ABUF_U32;
    float* ssum = (float*)(sm + STAT_OFF);
    float* ssq  = ssum + 128;

    const int tid = threadIdx.x;
    const int wid = tid >> 5, lane = tid & 31;
    const int gid = lane >> 2, tg = lane & 3;
    const int wm = wid >> 2, wn = wid & 3;
    const int m0 = wm * 32, n0 = wn * 32;
    uint32_t* stg = sm + STG_OFF + wid * 160;  // 8 rows x 20 half2-words

    // B = W0[:128,:] tf32 bits, [n][perm(k)]
    for (int i = tid; i < 128 * 128; i += 512) {
        int k = i >> 7, n = i & 127;
        Bs[n * BS_STRIDE + permk(k)] = tf32u(W0[i]);
    }
    if (tid < HH) { ssum[tid] = 0.f; ssq[tid] = 0.f; }

    // per-thread BN accumulators; col(nt,h) = n0 + nt*8 + tg*2 + h
    float ps[8], pq[8];
#pragma unroll
    for (int i = 0; i < 8; i++) { ps[i] = 0.f; pq[i] = 0.f; }

    // prologue: produce first tile into As0
    produce128(As0, nf, rowv, colv, blockIdx.x, wid, lane);

    int it = 0;
    for (int tile = blockIdx.x; tile < NT; tile += GRID1, it++) {
        uint32_t* Ab = (it & 1) ? As1 : As0;
        uint32_t* An = (it & 1) ? As0 : As1;
        __syncthreads();   // Ab fully produced; prior iter fully done

        // prefetch etype for this warp's 4 epilogue chunks (hides under MMA)
        int et4[4];
#pragma unroll
        for (int q = 0; q < 4; q++) {
            const int row = m0 + (q >> 1) * 16 + (q & 1) * 8 + gid;
            const int e = tile * 128 + row;
            et4[q] = (e < EN) ? etype[e] : 0;
        }

        // ---- MMA: 2 m-tiles x 4 n-tiles x 16 k-tiles ----
        float acc[2][4][4];
#pragma unroll
        for (int mt = 0; mt < 2; mt++)
#pragma unroll
            for (int nt = 0; nt < 4; nt++)
#pragma unroll
                for (int r = 0; r < 4; r++) acc[mt][nt][r] = 0.f;

#pragma unroll
        for (int kt = 0; kt < 16; kt++) {
            const int k0 = kt * 8;
            uint32_t afr[2][4];
#pragma unroll
            for (int mt = 0; mt < 2; mt++) {
                const uint32_t* ab = Ab + (m0 + mt * 16 + gid) * AS_STRIDE + k0 + tg;
                afr[mt][0] = ab[0];
                afr[mt][1] = ab[8 * AS_STRIDE];
                afr[mt][2] = ab[4];
                afr[mt][3] = ab[8 * AS_STRIDE + 4];
            }
            uint32_t bfr[4][2];
#pragma unroll
            for (int nt = 0; nt < 4; nt++) {
                uint2 bb = *(const uint2*)(Bs + (n0 + nt * 8 + gid) * BS_STRIDE
                                           + k0 + tg * 2);
                bfr[nt][0] = bb.x;
                bfr[nt][1] = bb.y;
            }
#pragma unroll
            for (int mt = 0; mt < 2; mt++)
#pragma unroll
                for (int nt = 0; nt < 4; nt++)
                    mma_tf32(acc[mt][nt], afr[mt], bfr[nt]);
        }

        // ---- produce NEXT tile into the other buffer (no barrier needed) ----
        if (tile + GRID1 < NT)
            produce128(An, nf, rowv, colv, tile + GRID1, wid, lane);

        // ---- epilogue: + prec, stats fp32, fp16 stage, coalesced STG.128 ----
#pragma unroll
        for (int mt = 0; mt < 2; mt++) {
#pragma unroll
            for (int rr = 0; rr < 2; rr++) {
                const int rbase = tile * 128 + m0 + mt * 16 + rr * 8;
                const bool valid = (rbase + gid) < EN;
                if (valid) {
                    const int et = et4[mt * 2 + rr];
                    const float2* prow = (const float2*)(g_prec + et * HH);
#pragma unroll
                    for (int nt = 0; nt < 4; nt++) {
                        const int c2g = (n0 + nt * 8 + tg * 2) >> 1;
                        float2 p = prow[c2g];
                        float v0 = acc[mt][nt][rr * 2 + 0] + p.x;
                        float v1 = acc[mt][nt][rr * 2 + 1] + p.y;
                        __half2 hv = __floats2half2_rn(v0, v1);
                        stg[gid * 20 + nt * 4 + tg] = *(uint32_t*)&hv;
                        ps[nt * 2 + 0] += v0; pq[nt * 2 + 0] = fmaf(v0, v0, pq[nt * 2 + 0]);
                        ps[nt * 2 + 1] += v1; pq[nt * 2 + 1] = fmaf(v1, v1, pq[nt * 2 + 1]);
                    }
                }
                __syncwarp();
                {
                    const int r = lane >> 2;               // local row 0..7
                    const int c = lane & 3;                // 16-byte chunk idx
                    const int e = rbase + r;
                    if (e < EN) {
                        uint4 v = *(const uint4*)(stg + r * 20 + c * 4);
                        __stcs((uint4*)((uint32_t*)(g_h2 + (size_t)e * 64 + n0 / 2) + c * 4), v);
                    }
                }
                __syncwarp();
            }
        }
    }

    // ---- final BN stat reduction: regs -> smem -> global ----
    __syncthreads();
#pragma unroll
    for (int nt = 0; nt < 4; nt++) {
#pragma unroll
        for (int h = 0; h < 2; h++) {
            const int col = n0 + nt * 8 + tg * 2 + h;
            atomicAdd(&ssum[col], ps[nt * 2 + h]);
            atomicAdd(&ssq[col], pq[nt * 2 + h]);
        }
    }
    __syncthreads();
    if (tid < HH) {
        atomicAdd(&g_sum[tid], ssum[tid]);
        atomicAdd(&g_sumsq[tid], ssq[tid]);
    }
}

// ---------------- pass3: BN params in-block, 8 edges/warp-iter, fp16 reads ----
__global__ __launch_bounds__(256) void k_pass3(const int* __restrict__ colv,
                                               const float* __restrict__ W1,
                                               const float* __restrict__ b1,
                                               const float* __restrict__ gamma,
                                               const float* __restrict__ beta) {
    __shared__ float sgi[HH], ssh[HH];
    int tidb = threadIdx.x;
    if (tidb < HH) {
        float mu = g_sum[tidb] * (1.0f / EN);
        float var = g_sumsq[tidb] * (1.0f / EN) - mu * mu;
        float gi = gamma[tidb] * rsqrtf(var + 1e-5f);
        sgi[tidb] = gi;
        ssh[tidb] = beta[tidb] - mu * gi;
    }
    __syncthreads();

    const int lane = tidb & 31;
    const int warp = (blockIdx.x * blockDim.x + tidb) >> 5;
    const int nwarp = (gridDim.x * blockDim.x) >> 5;
    const float4 gi = *(const float4*)(sgi + lane * 4);
    const float4 sh = *(const float4*)(ssh + lane * 4);
    const float4 w1 = *(const float4*)(W1 + lane * 4);
    const float b1v = b1[0];

    for (int e = warp * 8; e < EN; e += nwarp * 8) {     // EN % 8 == 0
        // batch 8 row loads (MLP 8 per warp); 4 channels per lane (2x half2)
        uint2 hraw[8];
#pragma unroll
        for (int j = 0; j < 8; j++)
            hraw[j] = __ldcs((const uint2*)(g_h2 + (size_t)(e + j) * 64 + lane * 2));
        int4 cn4a, cn4b;
        if (lane == 0) {
            cn4a = *(const int4*)(colv + e);
            cn4b = *(const int4*)(colv + e + 4);
        }

        float sdot[8];
#pragma unroll
        for (int j = 0; j < 8; j++) {
            float2 hl = __half22float2(*(__half2*)&hraw[j].x);
            float2 hh = __half22float2(*(__half2*)&hraw[j].y);
            float t, l, s;
            t = fmaf(hl.x, gi.x, sh.x); l = fmaxf(t, 0.f) + 0.01f * fminf(t, 0.f); s = l * w1.x;
            t = fmaf(hl.y, gi.y, sh.y); l = fmaxf(t, 0.f) + 0.01f * fminf(t, 0.f); s = fmaf(l, w1.y, s);
            t = fmaf(hh.x, gi.z, sh.z); l = fmaxf(t, 0.f) + 0.01f * fminf(t, 0.f); s = fmaf(l, w1.z, s);
            t = fmaf(hh.y, gi.w, sh.w); l = fmaxf(t, 0.f) + 0.01f * fminf(t, 0.f); s = fmaf(l, w1.w, s);
            sdot[j] = s;
        }
#pragma unroll
        for (int j = 0; j < 8; j++) {
            sdot[j] += __shfl_xor_sync(0xffffffffu, sdot[j], 16);
            sdot[j] += __shfl_xor_sync(0xffffffffu, sdot[j], 8);
            sdot[j] += __shfl_xor_sync(0xffffffffu, sdot[j], 4);
            sdot[j] += __shfl_xor_sync(0xffffffffu, sdot[j], 2);
            sdot[j] += __shfl_xor_sync(0xffffffffu, sdot[j], 1);
        }
        if (lane == 0) {
            float ev8[8];
            const int cns[8] = {cn4a.x, cn4a.y, cn4a.z, cn4a.w,
                                cn4b.x, cn4b.y, cn4b.z, cn4b.w};
#pragma unroll
            for (int j = 0; j < 8; j++) {
                float wv = sdot[j] + b1v;
                if (g_flag[e + j]) wv = 0.5f * wv + 0.5f;
                ev8[j] = exp2f(wv * L2E);
            }
            *(float4*)(g_w + e) = make_float4(ev8[0], ev8[1], ev8[2], ev8[3]);
            *(float4*)(g_w + e + 4) = make_float4(ev8[4], ev8[5], ev8[6], ev8[7]);
#pragma unroll
            for (int j = 0; j < 8; j++)
                atomicAdd(&g_nsum[cns[j]], ev8[j]);
        }
    }
}

// ---------------- pass5: vectorized x4 ----------------
__global__ void k_pass5(const int* __restrict__ colv, float* __restrict__ out) {
    int e = (blockIdx.x * blockDim.x + threadIdx.x) * 4;
    if (e >= EN) return;
    float4 w4 = *(const float4*)(g_w + e);
    int4 c4 = *(const int4*)(colv + e);
    float4 o;
    o.x = w4.x / g_nsum[c4.x];
    o.y = w4.y / g_nsum[c4.y];
    o.z = w4.z / g_nsum[c4.z];
    o.w = w4.w / g_nsum[c4.w];
    o.x = (o.x > 1e-4f) ? o.x : 0.f;
    o.y = (o.y > 1e-4f) ? o.y : 0.f;
    o.z = (o.z > 1e-4f) ? o.z : 0.f;
    o.w = (o.w > 1e-4f) ? o.w : 0.f;
    *(float4*)(out + e) = o;
}

// ---------------- launch ----------------
extern "C" void kernel_launch(void* const* d_in, const int* in_sizes, int n_in,
                              void* d_out, int out_size) {
    const float* n_feat  = (const float*)d_in[0];
    const float* rel_emb = (const float*)d_in[1];
    const float* W0      = (const float*)d_in[2];
    const float* b0      = (const float*)d_in[3];
    const float* gamma   = (const float*)d_in[4];
    const float* beta    = (const float*)d_in[5];
    const float* W1      = (const float*)d_in[6];
    const float* b1      = (const float*)d_in[7];
    const int*   rowv    = (const int*)d_in[8];
    const int*   colv    = (const int*)d_in[9];
    const int*   etype   = (const int*)d_in[10];
    const int*   ori     = (const int*)d_in[11];
    float* out = (float*)d_out;

    const int smem1 = SMEM_U32 * 4;   // 216,064 B
    static bool attr_done = false;
    if (!attr_done) {
        cudaFuncSetAttribute(k_pass1, cudaFuncAttributeMaxDynamicSharedMemorySize, smem1);
        attr_done = true;
    }

    k_setup<<<(EN + 255) / 256, 256>>>(rel_emb, W0, b0);
    k_flag<<<(EORI + 255) / 256, 256>>>(ori);
    k_pass1<<<GRID1, 512, smem1>>>(n_feat, W0, rowv, colv, etype);
    k_pass3<<<2048, 256>>>(colv, W1, b1, gamma, beta);
    k_pass5<<<(EN / 4 + 255) / 256, 256>>>(colv, out);
}

// round 17
// speedup vs baseline: 1.4064x; 1.2093x over previous
#include <cuda_runtime.h>
#include <cuda_fp16.h>
#include <cstdint>
#include <cstddef>

// Problem constants
#define EN    1000000
#define NN    100000
#define EORI  200000
#define DD    128
#define RR    32
#define HH    128
#define NRELC 200
#define L2E   1.4426950408889634f

#define NT    7813          // ceil(EN/128)
#define GRID1 148

#define AST 72              // uint32 (half2) per As row; 288B ≡ 32 mod 128 -> LDS.64 clean
#define BST 72              // same for Bs

// smem offsets (uint32 units)
#define BS_OFF   0
#define AS_OFF   (128 * BST)                          // 9216
#define ABUF_U32 (128 * AST)                          // 9216
#define STAT_OFF (AS_OFF + 2 * ABUF_U32)              // 27648
#define STG_OFF  (STAT_OFF + 256)                     // 27904
#define SMEM_U32 (STG_OFF + 16 * 160)                 // 30464 -> 121856 B

// ---------------- scratch globals ----------------
__device__ __half2 g_h2[(size_t)EN * 64];  // 256 MB pre-BN activations (fp16)
__device__ float g_w[EN];                  // exp(w) per edge
__device__ float g_sum[HH];
__device__ float g_sumsq[HH];
__device__ float g_nsum[NN];               // per-node softmax denominator
__device__ unsigned char g_flag[EN];       // is-original-edge flag
__device__ float g_prec[NRELC * HH];

// ---------------- helpers ----------------
// m16n8k16 f16 MMA, fp32 accumulate
__device__ __forceinline__ void mma_f16(float c[4], uint32_t a0, uint32_t a1,
                                        uint32_t a2, uint32_t a3,
                                        uint32_t b0, uint32_t b1) {
    asm volatile(
        "mma.sync.aligned.m16n8k16.row.col.f32.f16.f16.f32 "
        "{%0,%1,%2,%3}, {%4,%5,%6,%7}, {%8,%9}, {%0,%1,%2,%3};"
        : "+f"(c[0]), "+f"(c[1]), "+f"(c[2]), "+f"(c[3])
        : "r"(a0), "r"(a1), "r"(a2), "r"(a3), "r"(b0), "r"(b1));
}
// pack kidx and kidx+4 adjacent within each 8-block
__device__ __forceinline__ int permk(int k) {
    return (k & ~7) | ((k & 3) << 1) | ((k >> 2) & 1);
}

// ---------------- setup kernels ----------------
__global__ void k_setup(const float* __restrict__ rel,
                        const float* __restrict__ W0,
                        const float* __restrict__ b0) {
    int i = blockIdx.x * blockDim.x + threadIdx.x;
    if (i < HH) { g_sum[i] = 0.f; g_sumsq[i] = 0.f; }
    if (i < NN) g_nsum[i] = 0.f;
    if (i < EN) g_flag[i] = 0;
    if (i < NRELC * HH) {
        int r = i / HH, c = i % HH;
        float s = b0[c];
#pragma unroll
        for (int k = 0; k < RR; k++)
            s = fmaf(rel[r * RR + k], W0[(DD + k) * HH + c], s);
        g_prec[i] = s;
    }
}
__global__ void k_flag(const int* __restrict__ ori) {
    int i = blockIdx.x * blockDim.x + threadIdx.x;
    if (i < EORI) g_flag[ori[i]] = 1;
}

// ---------------- pass1 ------------------------------------------------------
// Persistent 148 x 512. Tile = 128 edges x 128 ch, K = 128, fp16 MMA m16n8k16.
// Warp grid 4(m) x 4(n); warp tile 32x32. R13 order:
// sync -> MMA(Ab) -> produce(t+GRID -> An) -> epilogue.
// As/Bs fp16 half2, permk layout: A frag = 2 LDS.64, B frag = 1 LDS.64.

__device__ __forceinline__ void produce128(uint32_t* __restrict__ As,
                                           const float* __restrict__ nf,
                                           const int* __restrict__ rowv,
                                           const int* __restrict__ colv,
                                           int tile, int wid, int lane) {
    const int e0 = tile * 128 + wid * 8;
    int idx = 0;
    {
        int q = e0 + (lane & 7);
        q = (q < EN) ? q : (EN - 1);
        if (lane < 16) idx = (lane < 8) ? rowv[q] : colv[q];
    }
    // word offset for this lane's STS.64 (permk-interleaved pair layout)
    const int wpos = ((lane >> 2) << 3) + (((lane & 1) << 2) | (lane & 2));
    const bool hi2 = (lane & 2) != 0;
#pragma unroll 2
    for (int i = 0; i < 8; i++) {
        const int rn = __shfl_sync(0xffffffffu, idx, i);
        const int cn = __shfl_sync(0xffffffffu, idx, i + 8);
        float4 a = *(const float4*)(nf + (size_t)rn * DD + lane * 4);
        float4 b = *(const float4*)(nf + (size_t)cn * DD + lane * 4);
        float s0 = exp2f(-L2E * fabsf(a.x - b.x));
        float s1 = exp2f(-L2E * fabsf(a.y - b.y));
        float s2 = exp2f(-L2E * fabsf(a.z - b.z));
        float s3 = exp2f(-L2E * fabsf(a.w - b.w));
        __half2 h0 = __floats2half2_rn(s0, s1);   // kidx = 2*lane
        __half2 h1 = __floats2half2_rn(s2, s3);   // kidx = 2*lane+1
        uint32_t u0 = *(uint32_t*)&h0;
        uint32_t u1 = *(uint32_t*)&h1;
        uint32_t send = hi2 ? u0 : u1;
        uint32_t recv = __shfl_xor_sync(0xffffffffu, send, 2);
        uint2 st;
        st.x = hi2 ? recv : u0;
        st.y = hi2 ? u1 : recv;
        *(uint2*)(As + (wid * 8 + i) * AST + wpos) = st;
    }
}

__global__ __launch_bounds__(512, 1) void k_pass1(
    const float* __restrict__ nf,
    const float* __restrict__ W0,
    const int* __restrict__ rowv,
    const int* __restrict__ colv,
    const int* __restrict__ etype) {
    extern __shared__ uint32_t sm[];
    uint32_t* Bs = sm + BS_OFF;              // [128 n][BST] half2, permk kidx
    uint32_t* As0 = sm + AS_OFF;             // [128 m][AST] half2, permk kidx x2
    uint32_t* As1 = As0 + ABUF_U32;
    float* ssum = (float*)(sm + STAT_OFF);
    float* ssq  = ssum + 128;

    const int tid = threadIdx.x;
    const int wid = tid >> 5, lane = tid & 31;
    const int gid = lane >> 2, tg = lane & 3;
    const int wm = wid >> 2, wn = wid & 3;
    const int m0 = wm * 32, n0 = wn * 32;
    uint32_t* stg = sm + STG_OFF + wid * 160;  // 8 rows x 20 half2-words

    // Bs[n][permk(kidx)] = half2(W0[2kidx][n], W0[2kidx+1][n])  (n fast: coalesced)
    for (int i = tid; i < 128 * 64; i += 512) {
        int n = i & 127, kidx = i >> 7;
        __half2 hv = __floats2half2_rn(W0[(2 * kidx) * HH + n],
                                       W0[(2 * kidx + 1) * HH + n]);
        Bs[n * BST + permk(kidx)] = *(uint32_t*)&hv;
    }
    if (tid < HH) { ssum[tid] = 0.f; ssq[tid] = 0.f; }

    // per-thread BN accumulators; col(nt,h) = n0 + nt*8 + tg*2 + h
    float ps[8], pq[8];
#pragma unroll
    for (int i = 0; i < 8; i++) { ps[i] = 0.f; pq[i] = 0.f; }

    // prologue: produce first tile into As0
    produce128(As0, nf, rowv, colv, blockIdx.x, wid, lane);

    int it = 0;
    for (int tile = blockIdx.x; tile < NT; tile += GRID1, it++) {
        uint32_t* Ab = (it & 1) ? As1 : As0;
        uint32_t* An = (it & 1) ? As0 : As1;
        __syncthreads();   // Ab fully produced; prior iter fully done

        // prefetch etype for this warp's 4 epilogue chunks (hides under MMA)
        int et4[4];
#pragma unroll
        for (int q = 0; q < 4; q++) {
            const int row = m0 + (q >> 1) * 16 + (q & 1) * 8 + gid;
            const int e = tile * 128 + row;
            et4[q] = (e < EN) ? etype[e] : 0;
        }

        // ---- MMA: 2 m-tiles x 4 n-tiles x 8 k-tiles (K=16 each) ----
        float acc[2][4][4];
#pragma unroll
        for (int mt = 0; mt < 2; mt++)
#pragma unroll
            for (int nt = 0; nt < 4; nt++)
#pragma unroll
                for (int r = 0; r < 4; r++) acc[mt][nt][r] = 0.f;

#pragma unroll
        for (int kt = 0; kt < 8; kt++) {
            const int k0 = kt * 8;
            uint2 au[2][2];
#pragma unroll
            for (int mt = 0; mt < 2; mt++) {
                const uint32_t* ab = Ab + (m0 + mt * 16 + gid) * AST + k0 + tg * 2;
                au[mt][0] = *(const uint2*)ab;              // {a0, a2} row gid
                au[mt][1] = *(const uint2*)(ab + 8 * AST);  // {a1, a3} row gid+8
            }
            uint2 bu[4];
#pragma unroll
            for (int nt = 0; nt < 4; nt++)
                bu[nt] = *(const uint2*)(Bs + (n0 + nt * 8 + gid) * BST + k0 + tg * 2);
#pragma unroll
            for (int mt = 0; mt < 2; mt++)
#pragma unroll
                for (int nt = 0; nt < 4; nt++)
                    mma_f16(acc[mt][nt], au[mt][0].x, au[mt][1].x,
                            au[mt][0].y, au[mt][1].y, bu[nt].x, bu[nt].y);
        }

        // ---- produce NEXT tile into the other buffer (no barrier needed) ----
        if (tile + GRID1 < NT)
            produce128(An, nf, rowv, colv, tile + GRID1, wid, lane);

        // ---- epilogue: + prec, stats fp32, fp16 stage, coalesced STG.128 ----
#pragma unroll
        for (int mt = 0; mt < 2; mt++) {
#pragma unroll
            for (int rr = 0; rr < 2; rr++) {
                const int rbase = tile * 128 + m0 + mt * 16 + rr * 8;
                const bool valid = (rbase + gid) < EN;
                if (valid) {
                    const int et = et4[mt * 2 + rr];
                    const float2* prow = (const float2*)(g_prec + et * HH);
#pragma unroll
                    for (int nt = 0; nt < 4; nt++) {
                        const int c2g = (n0 + nt * 8 + tg * 2) >> 1;
                        float2 p = prow[c2g];
                        float v0 = acc[mt][nt][rr * 2 + 0] + p.x;
                        float v1 = acc[mt][nt][rr * 2 + 1] + p.y;
                        __half2 hv = __floats2half2_rn(v0, v1);
                        stg[gid * 20 + nt * 4 + tg] = *(uint32_t*)&hv;
                        ps[nt * 2 + 0] += v0; pq[nt * 2 + 0] = fmaf(v0, v0, pq[nt * 2 + 0]);
                        ps[nt * 2 + 1] += v1; pq[nt * 2 + 1] = fmaf(v1, v1, pq[nt * 2 + 1]);
                    }
                }
                __syncwarp();
                {
                    const int r = lane >> 2;               // local row 0..7
                    const int c = lane & 3;                // 16-byte chunk idx
                    const int e = rbase + r;
                    if (e < EN) {
                        uint4 v = *(const uint4*)(stg + r * 20 + c * 4);
                        __stcs((uint4*)((uint32_t*)(g_h2 + (size_t)e * 64 + n0 / 2) + c * 4), v);
                    }
                }
                __syncwarp();
            }
        }
    }

    // ---- final BN stat reduction: regs -> smem -> global ----
    __syncthreads();
#pragma unroll
    for (int nt = 0; nt < 4; nt++) {
#pragma unroll
        for (int h = 0; h < 2; h++) {
            const int col = n0 + nt * 8 + tg * 2 + h;
            atomicAdd(&ssum[col], ps[nt * 2 + h]);
            atomicAdd(&ssq[col], pq[nt * 2 + h]);
        }
    }
    __syncthreads();
    if (tid < HH) {
        atomicAdd(&g_sum[tid], ssum[tid]);
        atomicAdd(&g_sumsq[tid], ssq[tid]);
    }
}

// ---------------- pass3: BN in-block, 8 edges/warp-iter, 9-shfl tree reduce ---
__global__ __launch_bounds__(256) void k_pass3(const int* __restrict__ colv,
                                               const float* __restrict__ W1,
                                               const float* __restrict__ b1,
                                               const float* __restrict__ gamma,
                                               const float* __restrict__ beta) {
    __shared__ float sgi[HH], ssh[HH];
    int tidb = threadIdx.x;
    if (tidb < HH) {
        float mu = g_sum[tidb] * (1.0f / EN);
        float var = g_sumsq[tidb] * (1.0f / EN) - mu * mu;
        float gi = gamma[tidb] * rsqrtf(var + 1e-5f);
        sgi[tidb] = gi;
        ssh[tidb] = beta[tidb] - mu * gi;
    }
    __syncthreads();

    const int lane = tidb & 31;
    const int warp = (blockIdx.x * blockDim.x + tidb) >> 5;
    const int nwarp = (gridDim.x * blockDim.x) >> 5;
    const float4 gi = *(const float4*)(sgi + lane * 4);
    const float4 sh = *(const float4*)(ssh + lane * 4);
    const float4 w1 = *(const float4*)(W1 + lane * 4);
    const float b1v = b1[0];
    const bool b16 = (lane & 16) != 0;
    const bool b8 = (lane & 8) != 0;
    const bool b4 = (lane & 4) != 0;

    for (int e = warp * 8; e < EN; e += nwarp * 8) {     // EN % 8 == 0
        uint2 hraw[8];
#pragma unroll
        for (int j = 0; j < 8; j++)
            hraw[j] = __ldcs((const uint2*)(g_h2 + (size_t)(e + j) * 64 + lane * 2));

        float sdot[8];
#pragma unroll
        for (int j = 0; j < 8; j++) {
            float2 hl = __half22float2(*(__half2*)&hraw[j].x);
            float2 hh = __half22float2(*(__half2*)&hraw[j].y);
            float t, l, s;
            t = fmaf(hl.x, gi.x, sh.x); l = fmaxf(t, 0.f) + 0.01f * fminf(t, 0.f); s = l * w1.x;
            t = fmaf(hl.y, gi.y, sh.y); l = fmaxf(t, 0.f) + 0.01f * fminf(t, 0.f); s = fmaf(l, w1.y, s);
            t = fmaf(hh.x, gi.z, sh.z); l = fmaxf(t, 0.f) + 0.01f * fminf(t, 0.f); s = fmaf(l, w1.z, s);
            t = fmaf(hh.y, gi.w, sh.w); l = fmaxf(t, 0.f) + 0.01f * fminf(t, 0.f); s = fmaf(l, w1.w, s);
            sdot[j] = s;
        }
        // tree reduce: 8 edge-sums across 32 lanes in 9 shfls.
        // after: lane 4j holds the total for edge j.
        float w4[4];
#pragma unroll
        for (int r = 0; r < 4; r++) {
            float keep = b16 ? sdot[r + 4] : sdot[r];
            float send = b16 ? sdot[r] : sdot[r + 4];
            w4[r] = keep + __shfl_xor_sync(0xffffffffu, send, 16);
        }
        float w2[2];
#pragma unroll
        for (int r = 0; r < 2; r++) {
            float keep = b8 ? w4[r + 2] : w4[r];
            float send = b8 ? w4[r] : w4[r + 2];
            w2[r] = keep + __shfl_xor_sync(0xffffffffu, send, 8);
        }
        float y;
        {
            float keep = b4 ? w2[1] : w2[0];
            float send = b4 ? w2[0] : w2[1];
            y = keep + __shfl_xor_sync(0xffffffffu, send, 4);
        }
        y += __shfl_xor_sync(0xffffffffu, y, 2);
        y += __shfl_xor_sync(0xffffffffu, y, 1);

        if ((lane & 3) == 0) {
            const int j = lane >> 2;
            const int ej = e + j;
            float wv = y + b1v;
            if (g_flag[ej]) wv = 0.5f * wv + 0.5f;
            float ev = exp2f(wv * L2E);
            g_w[ej] = ev;
            atomicAdd(&g_nsum[colv[ej]], ev);
        }
    }
}

// ---------------- pass5: vectorized x4 ----------------
__global__ void k_pass5(const int* __restrict__ colv, float* __restrict__ out) {
    int e = (blockIdx.x * blockDim.x + threadIdx.x) * 4;
    if (e >= EN) return;
    float4 w4 = *(const float4*)(g_w + e);
    int4 c4 = *(const int4*)(colv + e);
    float4 o;
    o.x = w4.x / g_nsum[c4.x];
    o.y = w4.y / g_nsum[c4.y];
    o.z = w4.z / g_nsum[c4.z];
    o.w = w4.w / g_nsum[c4.w];
    o.x = (o.x > 1e-4f) ? o.x : 0.f;
    o.y = (o.y > 1e-4f) ? o.y : 0.f;
    o.z = (o.z > 1e-4f) ? o.z : 0.f;
    o.w = (o.w > 1e-4f) ? o.w : 0.f;
    *(float4*)(out + e) = o;
}

// ---------------- launch ----------------
extern "C" void kernel_launch(void* const* d_in, const int* in_sizes, int n_in,
                              void* d_out, int out_size) {
    const float* n_feat  = (const float*)d_in[0];
    const float* rel_emb = (const float*)d_in[1];
    const float* W0      = (const float*)d_in[2];
    const float* b0      = (const float*)d_in[3];
    const float* gamma   = (const float*)d_in[4];
    const float* beta    = (const float*)d_in[5];
    const float* W1      = (const float*)d_in[6];
    const float* b1      = (const float*)d_in[7];
    const int*   rowv    = (const int*)d_in[8];
    const int*   colv    = (const int*)d_in[9];
    const int*   etype   = (const int*)d_in[10];
    const int*   ori     = (const int*)d_in[11];
    float* out = (float*)d_out;

    const int smem1 = SMEM_U32 * 4;   // 121,856 B
    static bool attr_done = false;
    if (!attr_done) {
        cudaFuncSetAttribute(k_pass1, cudaFuncAttributeMaxDynamicSharedMemorySize, smem1);
        attr_done = true;
    }

    k_setup<<<(EN + 255) / 256, 256>>>(rel_emb, W0, b0);
    k_flag<<<(EORI + 255) / 256, 256>>>(ori);
    k_pass1<<<GRID1, 512, smem1>>>(n_feat, W0, rowv, colv, etype);
    k_pass3<<<2048, 256>>>(colv, W1, b1, gamma, beta);
    k_pass5<<<(EN / 4 + 255) / 256, 256>>>(colv, out);
}